// round 2
// baseline (speedup 1.0000x reference)
#include <cuda_runtime.h>
#include <cstdint>
#include <cstddef>

#define LOG2E 1.4426950408889634f
#define LN2   0.6931471805599453f
#define NEGV  -100.0f

#define T_LEN 1024
#define V_N   8000
#define TPB   256
#define SEQB  64          // sequences per block (TPB/4)
#define TC    32          // timesteps per chunk
#define NCHUNK (T_LEN / TC)

// -------- device scratch (static allocation only, per harness rules) --------
__device__ __align__(16) float g_Bt[V_N * 4];   // log2-scaled log_B transposed [y][s]
__device__ float g_piA[4 + 16];                  // log2-scaled log_pi[4], log_A[4][4]

// ---------------------------- prep kernel ----------------------------------
// Replicates reference _log_params in fp32, then scales by log2(e).
__global__ void prep_kernel(const float* __restrict__ init_pi,
                            const float* __restrict__ init_A,
                            const float* __restrict__ init_B) {
    __shared__ float red[TPB];
    int tid = threadIdx.x;
    for (int s = 0; s < 4; ++s) {
        const float* row = init_B + (size_t)s * V_N;
        float mx = -1e30f;
        for (int i = tid; i < V_N; i += TPB) mx = fmaxf(mx, row[i]);
        red[tid] = mx; __syncthreads();
        for (int off = TPB / 2; off; off >>= 1) {
            if (tid < off) red[tid] = fmaxf(red[tid], red[tid + off]);
            __syncthreads();
        }
        mx = red[0]; __syncthreads();
        float sm = 0.f;
        for (int i = tid; i < V_N; i += TPB) sm += expf(row[i] - mx);
        red[tid] = sm; __syncthreads();
        for (int off = TPB / 2; off; off >>= 1) {
            if (tid < off) red[tid] += red[tid + off];
            __syncthreads();
        }
        float lse = mx + logf(red[0]); __syncthreads();
        for (int i = tid; i < V_N; i += TPB)
            g_Bt[i * 4 + s] = fmaxf(row[i] - lse, NEGV) * LOG2E;
    }
    if (tid == 0) {
        // pi: mask [0, -100, -100, 0], log_softmax over axis 0, clamp at -100
        float x[4];
        const float pim[4] = {0.f, NEGV, NEGV, 0.f};
        float mx = -1e30f;
        for (int i = 0; i < 4; ++i) { x[i] = init_pi[i] + pim[i]; mx = fmaxf(mx, x[i]); }
        float sm = 0.f;
        for (int i = 0; i < 4; ++i) sm += expf(x[i] - mx);
        float lse = mx + logf(sm);
        for (int i = 0; i < 4; ++i) g_piA[i] = fmaxf(x[i] - lse, NEGV) * LOG2E;
        // A with pattern mask, log_softmax along rows, clamp at -100
        const int pat[16] = {0,1,1,0, 0,1,1,0, 1,0,0,1, 1,0,0,1};
        for (int r = 0; r < 4; ++r) {
            float y[4]; float m2 = -1e30f;
            for (int j = 0; j < 4; ++j) {
                y[j] = init_A[r * 4 + j] + (pat[r * 4 + j] ? 0.f : NEGV);
                m2 = fmaxf(m2, y[j]);
            }
            float s2 = 0.f;
            for (int j = 0; j < 4; ++j) s2 += expf(y[j] - m2);
            float l2 = m2 + logf(s2);
            for (int j = 0; j < 4; ++j)
                g_piA[4 + r * 4 + j] = fmaxf(y[j] - l2, NEGV) * LOG2E;
        }
    }
}

// ---------------------------- main kernel -----------------------------------
__device__ __forceinline__ float fex2(float x) {
    float r; asm("ex2.approx.ftz.f32 %0, %1;" : "=f"(r) : "f"(x)); return r;
}
__device__ __forceinline__ float flg2(float x) {
    float r; asm("lg2.approx.ftz.f32 %0, %1;" : "=f"(r) : "f"(x)); return r;
}

struct SmemT {
    float bt[V_N * 5];          // 160000 B, stride-5 pad: bank = (5y+s)%32
    int   ytile[TC][SEQB + 1];  // 8448 B, pad 65 -> conflict-free both ways
    float mtile[TC][SEQB + 1];  // 8448 B
};                              // total 176896 B < 227 KB

__global__ void __launch_bounds__(TPB, 1)
hmm_kernel(const int* __restrict__ Y, const float* __restrict__ mask,
           float* __restrict__ out) {
    extern __shared__ char smraw[];
    SmemT& S = *reinterpret_cast<SmemT*>(smraw);

    const int tid  = threadIdx.x;
    const int lane = tid & 31;
    const int s    = tid & 3;       // my state
    const int seqL = tid >> 2;      // 0..63 local sequence
    const int seq0 = blockIdx.x * SEQB;

    // stage B table into padded smem (dense float4 LDG, conflict-free scalar STS)
    {
        const float4* src = reinterpret_cast<const float4*>(g_Bt);
        for (int i = tid; i < V_N; i += TPB) {
            float4 v = src[i];
            float* d = &S.bt[i * 5];
            d[0] = v.x; d[1] = v.y; d[2] = v.z; d[3] = v.w;
        }
    }

    // per-thread constants: my 2 predecessors and transition weights
    // new{0,3} <- old{2,3} ; new{1,2} <- old{0,1}
    const float pi2 = g_piA[s];
    const int   p0  = (s == 1 || s == 2) ? 0 : 2;
    const float A0  = g_piA[4 + p0 * 4 + s];
    const float A1  = g_piA[4 + (p0 + 1) * 4 + s];
    const int srcA  = (lane & ~3) | p0;
    const int srcB  = srcA + 1;

    // prefetch tile 0 (coalesced: 32 lanes cover one seq's 32 consecutive t)
    int   yreg[8];
    float mreg[8];
#pragma unroll
    for (int k = 0; k < 8; ++k) {
        int e = k * TPB + tid;
        int a = e >> 5, b = e & 31;
        int gi = (seq0 + a) * T_LEN + b;
        yreg[k] = Y[gi];
        mreg[k] = mask[gi];
    }

    float alpha = 0.f;
    // my output row: (n, s, t) -> row n*4+s == seq0*4 + tid
    size_t rowBase = (size_t)(seq0 * 4 + tid) * T_LEN;

    for (int c = 0; c < NCHUNK; ++c) {
        __syncthreads();            // previous tile fully consumed
#pragma unroll
        for (int k = 0; k < 8; ++k) {
            int e = k * TPB + tid;
            int a = e >> 5, b = e & 31;
            S.ytile[b][a] = yreg[k];
            S.mtile[b][a] = mreg[k];
        }
        __syncthreads();
        if (c + 1 < NCHUNK) {       // prefetch next tile; hidden under compute
#pragma unroll
            for (int k = 0; k < 8; ++k) {
                int e = k * TPB + tid;
                int a = e >> 5, b = e & 31;
                int gi = (seq0 + a) * T_LEN + (c + 1) * TC + b;
                yreg[k] = Y[gi];
                mreg[k] = mask[gi];
            }
        }

        float buf[TC];
        // prefetch emission + mask for step 0 of this chunk
        float e2 = S.bt[S.ytile[0][seqL] * 5 + s];
        float mk = S.mtile[0][seqL];
#pragma unroll
        for (int tt = 0; tt < TC; ++tt) {
            // prefetch next step's emission/mask (off the recurrence chain)
            float e2n = 0.f, mkn = 0.f;
            if (tt + 1 < TC) {
                e2n = S.bt[S.ytile[tt + 1][seqL] * 5 + s];
                mkn = S.mtile[tt + 1][seqL];
            }
            float ap0 = __shfl_sync(0xffffffffu, alpha, srcA);
            float ap1 = __shfl_sync(0xffffffffu, alpha, srcB);
            if (tt == 0 && c == 0) {
                alpha = pi2 + e2;                 // t = 0 init, no mask blend
            } else {
                float u  = ap0 + A0;
                float v  = ap1 + A1;
                float mx = fmaxf(u, v);
                float mn = fminf(u, v);
                float Q  = e2 - alpha;            // off-chain
                float P  = mx + Q;                // ready before lg2 finishes
                float L  = flg2(1.0f + fex2(mn - mx));
                alpha = fmaf(mk, L + P, alpha);   // mask blend
            }
            buf[tt] = alpha * LN2;                // back to natural log
            e2 = e2n; mk = mkn;
        }

        // flush my contiguous 128B output row segment (registers -> GMEM)
        float* orow = out + rowBase + c * TC;
#pragma unroll
        for (int j = 0; j < TC / 4; ++j) {
            float4 v = make_float4(buf[4 * j], buf[4 * j + 1],
                                   buf[4 * j + 2], buf[4 * j + 3]);
            *reinterpret_cast<float4*>(orow + 4 * j) = v;
        }
    }
}

// ---------------------------- launch ----------------------------------------
extern "C" void kernel_launch(void* const* d_in, const int* in_sizes, int n_in,
                              void* d_out, int out_size) {
    const int*   Y    = (const int*)d_in[0];
    const float* mask = (const float*)d_in[1];
    const float* pi   = (const float*)d_in[2];
    const float* A    = (const float*)d_in[3];
    const float* B    = (const float*)d_in[4];
    float* out = (float*)d_out;

    int N = in_sizes[0] / T_LEN;          // 8192

    cudaFuncSetAttribute(hmm_kernel,
                         cudaFuncAttributeMaxDynamicSharedMemorySize,
                         (int)sizeof(SmemT));

    prep_kernel<<<1, TPB>>>(pi, A, B);
    hmm_kernel<<<N / SEQB, TPB, sizeof(SmemT)>>>(Y, mask, out);
}